// round 11
// baseline (speedup 1.0000x reference)
#include <cuda_runtime.h>
#include <cuda_fp16.h>
#include <cstdint>

#define KC   512
#define DD   64
#define HW   4096
#define NB   32
#define NPIX (NB * HW)
#define XNUM (NPIX * DD)

#define PIXB   256                 // pixels per filter block
#define NBLK   (NPIX / PIXB)       // 512

__device__ int      g_idx[NPIX];
__device__ double   g_losssum;
__device__ float    g_wsq[KC];
__device__ uint32_t g_wh[32 * KC]; // [dpair][code] packed half2
__device__ int      g_flag[NPIX];
__device__ int      g_nflag;

// smem byte offsets for the filter kernel
#define W_OFF   0                          // [32][516] half2 words = 66048 B
#define X_OFF   66048                      // [32][256] half2 words = 32768 B
#define WSQ_OFF 98816                      // [512] f32
#define S1_OFF  100864                     // [256] f32
#define RB_OFF  101888                     // [4][256] f32 best
#define RS_OFF  105984                     // [4][256] f32 second
#define RI_OFF  110080                     // [4][256] i32 idx
#define SM_FILT 114176

__device__ __forceinline__ uint32_t packh2(float lo, float hi) {
    const __half2 h = __floats2half2_rn(lo, hi);
    return *(const uint32_t*)&h;
}
__device__ __forceinline__ uint32_t hmul2u(uint32_t a, uint32_t b) {
    uint32_t r;
    asm("mul.rn.f16x2 %0, %1, %2;" : "=r"(r) : "r"(a), "r"(b));
    return r;
}
__device__ __forceinline__ uint32_t hfma2u(uint32_t a, uint32_t b, uint32_t c) {
    uint32_t r;
    asm("fma.rn.f16x2 %0, %1, %2, %3;" : "=r"(r) : "r"(a), "r"(b), "r"(c));
    return r;
}
__device__ __forceinline__ uint32_t hadd2u(uint32_t a, uint32_t b) {
    uint32_t r;
    asm("add.rn.f16x2 %0, %1, %2;" : "=r"(r) : "r"(a), "r"(b));
    return r;
}
__device__ __forceinline__ float h2sum_f32(uint32_t h) {
    const __half2 v = *(const __half2*)&h;
    return __fadd_rn(__low2float(v), __high2float(v));
}

// Reference fp32 reduction tree for 64 elements (vec=2 + butterfly).
__device__ __forceinline__ float sumsq_tree64(const float* v) {
    float p[32];
#pragma unroll
    for (int t = 0; t < 32; t++) {
        float a = __fmul_rn(v[2 * t], v[2 * t]);
        float b = __fmul_rn(v[2 * t + 1], v[2 * t + 1]);
        p[t] = __fadd_rn(a, b);
    }
#pragma unroll
    for (int off = 16; off >= 1; off >>= 1)
#pragma unroll
        for (int l = 0; l < 16; l++)
            if (l < off) p[l] = __fadd_rn(p[l], p[l + off]);
    return p[0];
}

// ---------------------------------------------------------------------------
// K1: wsq (bit-exact tree), packed fp16 codebook, flag reset
// ---------------------------------------------------------------------------
__global__ void vq_prep(const float* __restrict__ w)
{
    const int k = threadIdx.x;
    if (k < KC) {
        float v[DD];
#pragma unroll
        for (int d = 0; d < DD; d++) v[d] = w[k * DD + d];
        g_wsq[k] = sumsq_tree64(v);
#pragma unroll
        for (int dp = 0; dp < 32; dp++)
            g_wh[dp * KC + k] = packh2(v[2 * dp], v[2 * dp + 1]);
    }
    if (k == 0) g_nflag = 0;
}

// ---------------------------------------------------------------------------
// K2: HFMA2 filter (128 MAC/cyc/SM) + fused enc zero-fill.
// 256 thr = 64 pixel-groups x 4 code-groups; thread tile 4px x 4codes,
// 4-way split half2 accumulators, worst-case-safe flagging threshold.
// ---------------------------------------------------------------------------
__global__ void __launch_bounds__(256, 2)
vq_mma_filter(const float* __restrict__ x,
              int* __restrict__ gidx, float* __restrict__ out_idx,
              float* __restrict__ out_enc)
{
    extern __shared__ char smc[];
    uint32_t* w_s   = (uint32_t*)(smc + W_OFF);    // [32][516]
    uint32_t* x_s   = (uint32_t*)(smc + X_OFF);    // [32][256]
    float*    wsq_s = (float*)(smc + WSQ_OFF);
    float*    s1h   = (float*)(smc + S1_OFF);
    float*    rb    = (float*)(smc + RB_OFF);
    float*    rs    = (float*)(smc + RS_OFF);
    int*      ri    = (int*)(smc + RI_OFF);

    const int tid = threadIdx.x;
    const int n0  = blockIdx.x * PIXB;
    const int b   = n0 >> 12;
    const int hw0 = n0 & 4095;

    // ---- codebook (prepacked) -> SMEM stride 516
    {
        const uint4* src = (const uint4*)g_wh;
        for (int i = tid; i < 32 * KC / 4; i += 256) {
            const int dp = (i * 4) >> 9, c = (i * 4) & 511;
            *(uint4*)&w_s[dp * 516 + c] = src[i];
        }
        for (int i = tid; i < KC; i += 256) wsq_s[i] = g_wsq[i];
    }
    // ---- x tile -> packed half2 [dpair][pixel]; per-pixel L1 norm
    {
        const float* xg = x + (size_t)b * DD * HW + hw0;
        const int p = tid;
        float s1 = 0.f;
#pragma unroll 8
        for (int dp = 0; dp < 32; dp++) {
            const float v0 = xg[(size_t)(2 * dp) * HW + p];
            const float v1 = xg[(size_t)(2 * dp + 1) * HW + p];
            s1 += fabsf(v0) + fabsf(v1);
            x_s[dp * 256 + p] = packh2(v0, v1);
        }
        s1h[p] = s1;
    }
    // ---- enc zero-fill setup (aligned-peeled float4 body)
    float* encb = out_enc + (size_t)n0 * KC;
    const unsigned mis = (unsigned)((unsigned long long)(uintptr_t)encb & 15ull);
    const int head  = (int)(((16u - mis) & 15u) >> 2);
    float4*  ez     = (float4*)(encb + head);
    const int body4 = (PIXB * KC - head) >> 2;
    const int tail  = (PIXB * KC - head) & 3;
    if (tid == 0) {
        for (int i = 0; i < head; i++) encb[i] = 0.f;
        for (int i = 0; i < tail; i++) encb[head + body4 * 4 + i] = 0.f;
    }
    __syncthreads();

    const int pg  = tid & 63;        // pixel group (4 px)
    const int cg  = tid >> 6;        // code group
    const int px0 = pg * 4;
    const float4 z4 = make_float4(0.f, 0.f, 0.f, 0.f);

    float best[4] = {3.4e38f, 3.4e38f, 3.4e38f, 3.4e38f};
    float sec[4]  = {3.4e38f, 3.4e38f, 3.4e38f, 3.4e38f};
    int   bi[4]   = {0, 0, 0, 0};

    int ktile = 0;
    for (int kt = 0; kt < KC; kt += 16, ktile++) {
        // interleaved enc zero stores (4 per thread per k-tile)
#pragma unroll
        for (int j = 0; j < 4; j++) {
            const int idx = (ktile * 4 + j) * 256 + tid;
            if (idx < body4) ez[idx] = z4;
        }

        const int kbase = kt + cg * 4;
        uint32_t acc[4][4][4];   // [code][pixel][split]

        // peel dpairs 0..3: initialize splits with mul
#pragma unroll
        for (int s = 0; s < 4; s++) {
            const uint4 xv = *(const uint4*)&x_s[s * 256 + px0];
            const uint4 wv = *(const uint4*)&w_s[s * 516 + kbase];
            const uint32_t xa[4] = {xv.x, xv.y, xv.z, xv.w};
            const uint32_t wa[4] = {wv.x, wv.y, wv.z, wv.w};
#pragma unroll
            for (int c = 0; c < 4; c++)
#pragma unroll
                for (int p = 0; p < 4; p++)
                    acc[c][p][s] = hmul2u(xa[p], wa[c]);
        }
#pragma unroll 4
        for (int dp = 4; dp < 32; dp++) {
            const int s = dp & 3;
            const uint4 xv = *(const uint4*)&x_s[dp * 256 + px0];
            const uint4 wv = *(const uint4*)&w_s[dp * 516 + kbase];
            const uint32_t xa[4] = {xv.x, xv.y, xv.z, xv.w};
            const uint32_t wa[4] = {wv.x, wv.y, wv.z, wv.w};
#pragma unroll
            for (int c = 0; c < 4; c++)
#pragma unroll
                for (int p = 0; p < 4; p++)
                    acc[c][p][s] = hfma2u(xa[p], wa[c], acc[c][p][s]);
        }
        // epilogue: combine splits, fp32 cross-lane, top-2 update
#pragma unroll
        for (int c = 0; c < 4; c++) {
            const int   k   = kbase + c;
            const float wsq = wsq_s[k];
#pragma unroll
            for (int p = 0; p < 4; p++) {
                const uint32_t h01 = hadd2u(acc[c][p][0], acc[c][p][1]);
                const uint32_t h23 = hadd2u(acc[c][p][2], acc[c][p][3]);
                const uint32_t h   = hadd2u(h01, h23);
                const float dot  = h2sum_f32(h);
                const float dist = __fmaf_rn(-2.f, dot, wsq);
                if (dist < best[p]) { sec[p] = best[p]; best[p] = dist; bi[p] = k; }
                else if (dist < sec[p]) sec[p] = dist;
            }
        }
    }

    // cross code-group merge via SMEM
#pragma unroll
    for (int p = 0; p < 4; p++) {
        rb[cg * 256 + px0 + p] = best[p];
        rs[cg * 256 + px0 + p] = sec[p];
        ri[cg * 256 + px0 + p] = bi[p];
    }
    __syncthreads();
    {
        const int p = tid;
        float bb = 3.4e38f, ss = 3.4e38f;
        int   ii = 0;
#pragma unroll
        for (int g = 0; g < 4; g++) {
            const float bg = rb[g * 256 + p];
            const float sg = rs[g * 256 + p];
            const int   ig = ri[g * 256 + p];
            if (bg < bb || (bg == bb && ig < ii)) {
                ss = fminf(ss, bb); bb = bg; ii = ig;
            } else {
                ss = fminf(ss, bg);
            }
            ss = fminf(ss, sg);
        }
        gidx[n0 + p]    = ii;
        out_idx[n0 + p] = (float)ii;

        // worst-case-safe flag: gap < 1.2e-4*S1 + 1e-4
        const float T = __fmaf_rn(1.2e-4f, s1h[p], 1.0e-4f);
        const bool flag = (__fsub_rn(ss, bb) < T);
        const unsigned m = __ballot_sync(0xffffffffu, flag);
        const int lane = tid & 31;
        int base = 0;
        if (m) {
            const int leader = __ffs(m) - 1;
            if (lane == leader) base = atomicAdd(&g_nflag, __popc(m));
            base = __shfl_sync(0xffffffffu, base, leader);
            if (flag) {
                const int rank = __popc(m & ((1u << lane) - 1u));
                g_flag[base + rank] = n0 + p;
            }
        }
    }
}

// ---------------------------------------------------------------------------
// K3: bit-exact fallback for flagged pixels (1 warp per pixel, wide grid).
// ---------------------------------------------------------------------------
__global__ void __launch_bounds__(256, 1)
vq_fallback(const float* __restrict__ x, const float* __restrict__ w,
            int* __restrict__ gidx, float* __restrict__ out_idx)
{
    if (blockIdx.x * 8 >= g_nflag) return;
    extern __shared__ char smc[];
    float* w_s   = (float*)smc;                          // [512*65] padded
    float* wsq_s = (float*)(smc + KC * 65 * 4);          // [512]
    float* xrow  = (float*)(smc + KC * 65 * 4 + KC * 4); // [8][64]
    const int tid = threadIdx.x, wid = tid >> 5, lane = tid & 31;

    for (int i = tid; i < KC * DD; i += 256) {
        const int k = i >> 6, d = i & 63;
        w_s[k * 65 + d] = w[i];
    }
    for (int i = tid; i < KC; i += 256) wsq_s[i] = g_wsq[i];
    __syncthreads();

    const int nflag = g_nflag;
    for (int f = blockIdx.x * 8 + wid; f < nflag; f += gridDim.x * 8) {
        const int n  = g_flag[f];
        const int b  = n >> 12, hw = n & 4095;
        const float* xp = x + (size_t)b * DD * HW + hw;
        xrow[wid * 64 + lane]      = xp[(size_t)lane * HW];
        xrow[wid * 64 + lane + 32] = xp[(size_t)(lane + 32) * HW];
        __syncwarp();
        float pa = __fmul_rn(xrow[wid * 64 + 2 * lane],     xrow[wid * 64 + 2 * lane]);
        float pb = __fmul_rn(xrow[wid * 64 + 2 * lane + 1], xrow[wid * 64 + 2 * lane + 1]);
        float pt = __fadd_rn(pa, pb);
#pragma unroll
        for (int off = 16; off >= 1; off >>= 1) {
            const float q = __shfl_down_sync(0xffffffffu, pt, off);
            pt = __fadd_rn(pt, q);
        }
        const float xsq = __shfl_sync(0xffffffffu, pt, 0);

        float bd = 3.4e38f; int bk = 0;
#pragma unroll 1
        for (int j = 0; j < 16; j++) {
            const int k = lane + 32 * j;
            float dot = 0.f;
#pragma unroll
            for (int d = 0; d < DD; d++)
                dot = __fmaf_rn(xrow[wid * 64 + d], w_s[k * 65 + d], dot);
            const float dist = __fsub_rn(__fadd_rn(xsq, wsq_s[k]), __fadd_rn(dot, dot));
            if (dist < bd) { bd = dist; bk = k; }
        }
#pragma unroll
        for (int off = 16; off >= 1; off >>= 1) {
            const float od = __shfl_down_sync(0xffffffffu, bd, off);
            const int   ok = __shfl_down_sync(0xffffffffu, bk, off);
            if (od < bd || (od == bd && ok < bk)) { bd = od; bk = ok; }
        }
        if (lane == 0) { gidx[n] = bk; out_idx[n] = (float)bk; }
        __syncwarp();
    }
}

// ---------------------------------------------------------------------------
// K4: quantized NCHW output (straight-through rounding), one-hot set, loss.
// ---------------------------------------------------------------------------
__global__ void __launch_bounds__(256)
vq_scatter(const float* __restrict__ x, const float* __restrict__ w,
           const int* __restrict__ gidx,
           float* __restrict__ out_q, float* __restrict__ out_enc,
           double* __restrict__ losssum)
{
    const int tid = threadIdx.x;
    const int n   = blockIdx.x * 256 + tid;
    const int k   = gidx[n];
    const int b   = n >> 12, hw = n & 4095;
    const float*  xp = x     + (size_t)b * DD * HW + hw;
    float*        qp = out_q + (size_t)b * DD * HW + hw;
    const float4* wr = (const float4*)(w + (size_t)k * DD);

    float s = 0.f;
#pragma unroll
    for (int j = 0; j < 16; j++) {
        const float4 wv = __ldg(wr + j);
        const float xv0 = xp[(size_t)(4 * j + 0) * HW];
        const float xv1 = xp[(size_t)(4 * j + 1) * HW];
        const float xv2 = xp[(size_t)(4 * j + 2) * HW];
        const float xv3 = xp[(size_t)(4 * j + 3) * HW];
        const float d0 = __fsub_rn(wv.x, xv0);
        const float d1 = __fsub_rn(wv.y, xv1);
        const float d2 = __fsub_rn(wv.z, xv2);
        const float d3 = __fsub_rn(wv.w, xv3);
        qp[(size_t)(4 * j + 0) * HW] = __fadd_rn(xv0, d0);
        qp[(size_t)(4 * j + 1) * HW] = __fadd_rn(xv1, d1);
        qp[(size_t)(4 * j + 2) * HW] = __fadd_rn(xv2, d2);
        qp[(size_t)(4 * j + 3) * HW] = __fadd_rn(xv3, d3);
        s = fmaf(d0, d0, s); s = fmaf(d1, d1, s);
        s = fmaf(d2, d2, s); s = fmaf(d3, d3, s);
    }
    out_enc[(size_t)n * KC + k] = 1.0f;

#pragma unroll
    for (int off = 16; off; off >>= 1) s += __shfl_down_sync(0xffffffffu, s, off);
    __shared__ float sred[8];
    if ((tid & 31) == 0) sred[tid >> 5] = s;
    __syncthreads();
    if (tid < 8) {
        float v = sred[tid];
#pragma unroll
        for (int off = 4; off; off >>= 1) v += __shfl_down_sync(0xffu, v, off);
        if (tid == 0) atomicAdd(losssum, (double)v);
    }
}

__global__ void vq_finalize(const double* __restrict__ losssum,
                            float* __restrict__ out_loss)
{
    out_loss[0] = (float)(2.0 * (*losssum) / (double)XNUM);
}

// ---------------------------------------------------------------------------
extern "C" void kernel_launch(void* const* d_in, const int* in_sizes, int n_in,
                              void* d_out, int out_size)
{
    const float* x = (const float*)d_in[0];   // [32, 64, 64, 64] NCHW
    const float* w = (const float*)d_in[1];   // [512, 64]

    float* out      = (float*)d_out;
    float* out_loss = out;
    float* out_q    = out + 1;
    float* out_enc  = out + 1 + (size_t)XNUM;
    float* out_idx  = out + 1 + (size_t)XNUM + (size_t)NPIX * KC;

    int*    gidx_ptr = nullptr;
    double* loss_ptr = nullptr;
    cudaGetSymbolAddress((void**)&gidx_ptr, g_idx);
    cudaGetSymbolAddress((void**)&loss_ptr, g_losssum);

    const int smem_fb = KC * 65 * 4 + KC * 4 + 8 * DD * 4;
    cudaFuncSetAttribute(vq_mma_filter, cudaFuncAttributeMaxDynamicSharedMemorySize, SM_FILT);
    cudaFuncSetAttribute(vq_fallback,   cudaFuncAttributeMaxDynamicSharedMemorySize, smem_fb);

    cudaMemsetAsync(loss_ptr, 0, sizeof(double), 0);

    vq_prep      <<<1, 512>>>(w);
    vq_mma_filter<<<NBLK, 256, SM_FILT>>>(x, gidx_ptr, out_idx, out_enc);
    vq_fallback  <<<512, 256, smem_fb>>>(x, w, gidx_ptr, out_idx);
    vq_scatter   <<<NPIX / 256, 256>>>(x, w, gidx_ptr, out_q, out_enc, loss_ptr);
    vq_finalize  <<<1, 1>>>(loss_ptr, out_loss);
}

// round 12
// speedup vs baseline: 3.4683x; 3.4683x over previous
#include <cuda_runtime.h>
#include <cuda_fp16.h>
#include <cstdint>

#define KC   512
#define DD   64
#define HW   4096
#define NB   32
#define NPIX (NB * HW)
#define XNUM (NPIX * DD)

#define TILE_M  128
#define NTILES  (NPIX / TILE_M)   // 1024

__device__ double g_losssum;
__device__ float  g_wsq[KC];
__device__ int    g_flag[NPIX];
__device__ int    g_nflag;

// smem word map for the fp16 MMA filter (stride-36 padded half2 tiles)
#define XS_OFF   0
#define WS_OFF   (XS_OFF + 128 * 36 * 4)     // 18432 B
#define WSQ_OFF  (WS_OFF + 512 * 36 * 4)     // 92160 B
#define S1_OFF   (WSQ_OFF + 512 * 4)         // 94208 B
#define SM_TOT   (S1_OFF + 256 * 4)          // 95232 B

__device__ __forceinline__ void mma_f16(float& c0, float& c1, float& c2, float& c3,
                                        uint32_t a0, uint32_t a1, uint32_t a2, uint32_t a3,
                                        uint32_t b0, uint32_t b1) {
    asm volatile(
        "mma.sync.aligned.m16n8k16.row.col.f32.f16.f16.f32 "
        "{%0,%1,%2,%3}, {%4,%5,%6,%7}, {%8,%9}, {%0,%1,%2,%3};"
        : "+f"(c0), "+f"(c1), "+f"(c2), "+f"(c3)
        : "r"(a0), "r"(a1), "r"(a2), "r"(a3), "r"(b0), "r"(b1));
}
__device__ __forceinline__ uint32_t packh2(float lo, float hi) {
    const __half2 h = __floats2half2_rn(lo, hi);
    return *(const uint32_t*)&h;
}

// Reference fp32 reduction tree for 64 elements (vec=2 + butterfly).
__device__ __forceinline__ float sumsq_tree64(const float* v) {
    float p[32];
#pragma unroll
    for (int t = 0; t < 32; t++) {
        float a = __fmul_rn(v[2 * t], v[2 * t]);
        float b = __fmul_rn(v[2 * t + 1], v[2 * t + 1]);
        p[t] = __fadd_rn(a, b);
    }
#pragma unroll
    for (int off = 16; off >= 1; off >>= 1)
#pragma unroll
        for (int l = 0; l < 16; l++)
            if (l < off) p[l] = __fadd_rn(p[l], p[l + off]);
    return p[0];
}

// ---------------------------------------------------------------------------
// K1: per-code squared norms (bit-exact tree) + flag counter reset
// ---------------------------------------------------------------------------
__global__ void vq_prep(const float* __restrict__ w)
{
    const int k = threadIdx.x;
    if (k < KC) {
        float v[DD];
#pragma unroll
        for (int d = 0; d < DD; d++) v[d] = w[k * DD + d];
        g_wsq[k] = sumsq_tree64(v);
    }
    if (k == 0) g_nflag = 0;
}

// ---------------------------------------------------------------------------
// K2: fp16 m16n8k16 mma.sync filter + fused enc zero-fill + fused scatter
// (q write, enc one-hot, loss) for unflagged pixels.
// Block = 256 thr = 8 warps; warp handles 16 pixels x 512 codes.
// ---------------------------------------------------------------------------
__global__ void __launch_bounds__(256, 2)
vq_mma_filter(const float* __restrict__ x, const float* __restrict__ w,
              float* __restrict__ out_idx, float* __restrict__ out_q,
              float* __restrict__ out_enc, double* __restrict__ losssum)
{
    extern __shared__ char smc[];
    uint32_t* x_s   = (uint32_t*)(smc + XS_OFF);   // [128][36] half2 words
    uint32_t* w_s   = (uint32_t*)(smc + WS_OFF);   // [512][36] half2 words
    float*    wsq_s = (float*)(smc + WSQ_OFF);     // [512]
    float*    s1h   = (float*)(smc + S1_OFF);      // [256]

    const int tid = threadIdx.x;
    const int n0  = blockIdx.x * TILE_M;
    const int b   = n0 >> 12;
    const int hw0 = n0 & 4095;

    // ---- codebook -> packed fp16 SMEM (row stride 36 words) + wsq
    for (int i = tid; i < KC * 32; i += 256) {
        const int k = i >> 5, j = i & 31;
        const float2 v = *(const float2*)(w + k * DD + 2 * j);
        w_s[k * 36 + j] = packh2(v.x, v.y);
    }
    for (int i = tid; i < KC; i += 256) wsq_s[i] = g_wsq[i];

    // ---- x tile -> packed fp16 SMEM [p][d/2]; per-pixel L1-norm halves
    {
        const float* xg = x + (size_t)b * DD * HW + hw0;
        const int p = tid & 127, h = tid >> 7;   // h selects d-half [32h,32h+32)
        float s1 = 0.f;
#pragma unroll 4
        for (int j = 0; j < 16; j++) {
            const int d = 32 * h + 2 * j;
            const float v0 = xg[(size_t)d * HW + p];
            const float v1 = xg[(size_t)(d + 1) * HW + p];
            s1 += fabsf(v0) + fabsf(v1);
            x_s[p * 36 + 16 * h + j] = packh2(v0, v1);
        }
        s1h[tid] = s1;
    }

    // ---- fused enc zero-fill for rows n0..n0+127 (aligned-peeled float4)
    {
        float* encb = out_enc + (size_t)n0 * KC;
        const unsigned mis = (unsigned)((unsigned long long)(uintptr_t)encb & 15ull);
        const int head  = (int)(((16u - mis) & 15u) >> 2);
        float4*  ez     = (float4*)(encb + head);
        const int body4 = (TILE_M * KC - head) >> 2;
        const int tail  = (TILE_M * KC - head) & 3;
        if (tid == 0) {
            for (int i = 0; i < head; i++) encb[i] = 0.f;
            for (int i = 0; i < tail; i++) encb[head + body4 * 4 + i] = 0.f;
        }
        const float4 z4 = make_float4(0.f, 0.f, 0.f, 0.f);
        for (int i = tid; i < body4; i += 256) ez[i] = z4;
    }
    __syncthreads();

    // ---- per-warp MMA: 16 pixels x 512 codes, K=64 via 4 k-steps of 16
    const int lane = tid & 31, wid = tid >> 5;
    const int gid  = lane >> 2, tI = lane & 3;
    const int r0   = wid * 16 + gid, r1 = r0 + 8;

    uint32_t A[4][4];
#pragma unroll
    for (int kk = 0; kk < 4; kk++) {
        A[kk][0] = x_s[r0 * 36 + 8 * kk + tI];
        A[kk][1] = x_s[r1 * 36 + 8 * kk + tI];
        A[kk][2] = x_s[r0 * 36 + 8 * kk + tI + 4];
        A[kk][3] = x_s[r1 * 36 + 8 * kk + tI + 4];
    }

    float best0 = 3.4e38f, sec0 = 3.4e38f, best1 = 3.4e38f, sec1 = 3.4e38f;
    int   bi0 = 0, bi1 = 0;

#pragma unroll 1
    for (int nt = 0; nt < 64; nt += 4) {
        float c[4][4];
#pragma unroll
        for (int q = 0; q < 4; q++)
#pragma unroll
            for (int f = 0; f < 4; f++) c[q][f] = 0.f;

#pragma unroll
        for (int kk = 0; kk < 4; kk++) {
#pragma unroll
            for (int q = 0; q < 4; q++) {
                const int row = (nt + q) * 8 + gid;
                const uint32_t b0 = w_s[row * 36 + 8 * kk + tI];
                const uint32_t b1 = w_s[row * 36 + 8 * kk + tI + 4];
                mma_f16(c[q][0], c[q][1], c[q][2], c[q][3],
                        A[kk][0], A[kk][1], A[kk][2], A[kk][3], b0, b1);
            }
        }
#pragma unroll
        for (int q = 0; q < 4; q++) {
            const int cb = (nt + q) * 8 + 2 * tI;
            const float w0 = wsq_s[cb], w1 = wsq_s[cb + 1];
            const float d00 = __fmaf_rn(-2.f, c[q][0], w0);
            const float d01 = __fmaf_rn(-2.f, c[q][1], w1);
            const float d10 = __fmaf_rn(-2.f, c[q][2], w0);
            const float d11 = __fmaf_rn(-2.f, c[q][3], w1);
            if (d00 < best0) { sec0 = best0; best0 = d00; bi0 = cb; }
            else if (d00 < sec0) sec0 = d00;
            if (d01 < best0) { sec0 = best0; best0 = d01; bi0 = cb + 1; }
            else if (d01 < sec0) sec0 = d01;
            if (d10 < best1) { sec1 = best1; best1 = d10; bi1 = cb; }
            else if (d10 < sec1) sec1 = d10;
            if (d11 < best1) { sec1 = best1; best1 = d11; bi1 = cb + 1; }
            else if (d11 < sec1) sec1 = d11;
        }
    }

    // merge top-2 across the 4 threads of each quad (butterfly xor 1, 2)
#pragma unroll
    for (int m = 1; m <= 2; m <<= 1) {
        float ob = __shfl_xor_sync(0xffffffffu, best0, m);
        float os = __shfl_xor_sync(0xffffffffu, sec0,  m);
        int  obi = __shfl_xor_sync(0xffffffffu, bi0,   m);
        if (ob < best0 || (ob == best0 && obi < bi0)) { sec0 = fminf(best0, os); best0 = ob; bi0 = obi; }
        else sec0 = fminf(sec0, ob);
        ob  = __shfl_xor_sync(0xffffffffu, best1, m);
        os  = __shfl_xor_sync(0xffffffffu, sec1,  m);
        obi = __shfl_xor_sync(0xffffffffu, bi1,   m);
        if (ob < best1 || (ob == best1 && obi < bi1)) { sec1 = fminf(best1, os); best1 = ob; bi1 = obi; }
        else sec1 = fminf(sec1, ob);
    }

    // publish per-pixel results to SMEM so each thread owns one pixel after sync
    // reuse x_s region (mainloop done): [128] idx, [128] flag
    int*   res_i = (int*)(smc + XS_OFF);
    int*   res_f = (int*)(smc + XS_OFF + 128 * 4);
    if (tI == 0) {
        const float S1a = s1h[r0] + s1h[r0 + 128];
        const float S1b = s1h[r1] + s1h[r1 + 128];
        res_i[r0] = bi0;
        res_i[r1] = bi1;
        res_f[r0] = (__fsub_rn(sec0, best0) < __fmaf_rn(1e-5f, S1a, 4e-5f));
        res_f[r1] = (__fsub_rn(sec1, best1) < __fmaf_rn(1e-5f, S1b, 4e-5f));
    }
    __syncthreads();   // also orders all enc zero-stores before one-hot below

    // ---- fused scatter: threads 0..127 each own pixel p = tid
    float s = 0.f;
    if (tid < TILE_M) {
        const int p    = tid;
        const int n    = n0 + p;
        const int ii   = res_i[p];
        const int flag = res_f[p];
        out_idx[n] = (float)ii;

        if (flag) {
            const unsigned m2 = __activemask();
            const int pos = atomicAdd(&g_nflag, 1);
            g_flag[pos] = n;
            (void)m2;
        } else {
            const float*  xp = x     + (size_t)b * DD * HW + hw0 + p;
            float*        qp = out_q + (size_t)b * DD * HW + hw0 + p;
            const float4* wr = (const float4*)(w + (size_t)ii * DD);
#pragma unroll
            for (int j = 0; j < 16; j++) {
                const float4 wv = __ldg(wr + j);
                const float xv0 = xp[(size_t)(4 * j + 0) * HW];
                const float xv1 = xp[(size_t)(4 * j + 1) * HW];
                const float xv2 = xp[(size_t)(4 * j + 2) * HW];
                const float xv3 = xp[(size_t)(4 * j + 3) * HW];
                const float d0 = __fsub_rn(wv.x, xv0);
                const float d1 = __fsub_rn(wv.y, xv1);
                const float d2 = __fsub_rn(wv.z, xv2);
                const float d3 = __fsub_rn(wv.w, xv3);
                qp[(size_t)(4 * j + 0) * HW] = __fadd_rn(xv0, d0);
                qp[(size_t)(4 * j + 1) * HW] = __fadd_rn(xv1, d1);
                qp[(size_t)(4 * j + 2) * HW] = __fadd_rn(xv2, d2);
                qp[(size_t)(4 * j + 3) * HW] = __fadd_rn(xv3, d3);
                s = fmaf(d0, d0, s); s = fmaf(d1, d1, s);
                s = fmaf(d2, d2, s); s = fmaf(d3, d3, s);
            }
            out_enc[(size_t)n * KC + ii] = 1.0f;
        }
    }
    // block loss reduction (threads >=128 contribute 0)
#pragma unroll
    for (int off = 16; off; off >>= 1) s += __shfl_down_sync(0xffffffffu, s, off);
    __shared__ float sred[8];
    if ((tid & 31) == 0) sred[tid >> 5] = s;
    __syncthreads();
    if (tid < 8) {
        float v = sred[tid];
#pragma unroll
        for (int off = 4; off; off >>= 1) v += __shfl_down_sync(0xffu, v, off);
        if (tid == 0 && v != 0.f) atomicAdd(losssum, (double)v);
    }
}

// ---------------------------------------------------------------------------
// K3: bit-exact fallback for flagged pixels (1 warp per pixel) + their
// q / enc one-hot / loss contribution.
// ---------------------------------------------------------------------------
__global__ void __launch_bounds__(256, 1)
vq_fallback(const float* __restrict__ x, const float* __restrict__ w,
            float* __restrict__ out_idx, float* __restrict__ out_q,
            float* __restrict__ out_enc, double* __restrict__ losssum)
{
    if (blockIdx.x * 8 >= g_nflag) return;
    extern __shared__ char smc[];
    float* w_s   = (float*)smc;                          // [512*65] padded
    float* wsq_s = (float*)(smc + KC * 65 * 4);          // [512]
    float* xrow  = (float*)(smc + KC * 65 * 4 + KC * 4); // [8][64]
    const int tid = threadIdx.x, wid = tid >> 5, lane = tid & 31;

    for (int i = tid; i < KC * DD; i += 256) {
        const int k = i >> 6, d = i & 63;
        w_s[k * 65 + d] = w[i];
    }
    for (int i = tid; i < KC; i += 256) wsq_s[i] = g_wsq[i];
    __syncthreads();

    const int nflag = g_nflag;
    for (int f = blockIdx.x * 8 + wid; f < nflag; f += gridDim.x * 8) {
        const int n  = g_flag[f];
        const int b  = n >> 12, hw = n & 4095;
        const float* xp = x + (size_t)b * DD * HW + hw;
        xrow[wid * 64 + lane]      = xp[(size_t)lane * HW];
        xrow[wid * 64 + lane + 32] = xp[(size_t)(lane + 32) * HW];
        __syncwarp();
        float pa = __fmul_rn(xrow[wid * 64 + 2 * lane],     xrow[wid * 64 + 2 * lane]);
        float pb = __fmul_rn(xrow[wid * 64 + 2 * lane + 1], xrow[wid * 64 + 2 * lane + 1]);
        float pt = __fadd_rn(pa, pb);
#pragma unroll
        for (int off = 16; off >= 1; off >>= 1) {
            const float q = __shfl_down_sync(0xffffffffu, pt, off);
            pt = __fadd_rn(pt, q);
        }
        const float xsq = __shfl_sync(0xffffffffu, pt, 0);

        float bd = 3.4e38f; int bk = 0;
#pragma unroll 1
        for (int j = 0; j < 16; j++) {
            const int k = lane + 32 * j;
            float dot = 0.f;
#pragma unroll
            for (int d = 0; d < DD; d++)
                dot = __fmaf_rn(xrow[wid * 64 + d], w_s[k * 65 + d], dot);
            const float dist = __fsub_rn(__fadd_rn(xsq, wsq_s[k]), __fadd_rn(dot, dot));
            if (dist < bd) { bd = dist; bk = k; }
        }
#pragma unroll
        for (int off = 16; off >= 1; off >>= 1) {
            const float od = __shfl_down_sync(0xffffffffu, bd, off);
            const int   ok = __shfl_down_sync(0xffffffffu, bk, off);
            if (od < bd || (od == bd && ok < bk)) { bd = od; bk = ok; }
        }
        bk = __shfl_sync(0xffffffffu, bk, 0);

        // write q (straight-through rounding), enc one-hot, loss for this pixel
        float* qp = out_q + (size_t)b * DD * HW + hw;
        const float xv0 = xrow[wid * 64 + lane];
        const float xv1 = xrow[wid * 64 + lane + 32];
        const float wv0 = w_s[bk * 65 + lane];
        const float wv1 = w_s[bk * 65 + lane + 32];
        const float d0  = __fsub_rn(wv0, xv0);
        const float d1  = __fsub_rn(wv1, xv1);
        qp[(size_t)lane * HW]        = __fadd_rn(xv0, d0);
        qp[(size_t)(lane + 32) * HW] = __fadd_rn(xv1, d1);
        float ls = fmaf(d1, d1, __fmul_rn(d0, d0));
#pragma unroll
        for (int off = 16; off >= 1; off >>= 1)
            ls += __shfl_down_sync(0xffffffffu, ls, off);
        if (lane == 0) {
            out_idx[n] = (float)bk;
            out_enc[(size_t)n * KC + bk] = 1.0f;
            atomicAdd(losssum, (double)ls);
        }
        __syncwarp();
    }
}

__global__ void vq_finalize(const double* __restrict__ losssum,
                            float* __restrict__ out_loss)
{
    out_loss[0] = (float)(2.0 * (*losssum) / (double)XNUM);
}

// ---------------------------------------------------------------------------
extern "C" void kernel_launch(void* const* d_in, const int* in_sizes, int n_in,
                              void* d_out, int out_size)
{
    const float* x = (const float*)d_in[0];   // [32, 64, 64, 64] NCHW
    const float* w = (const float*)d_in[1];   // [512, 64]

    float* out      = (float*)d_out;
    float* out_loss = out;
    float* out_q    = out + 1;
    float* out_enc  = out + 1 + (size_t)XNUM;
    float* out_idx  = out + 1 + (size_t)XNUM + (size_t)NPIX * KC;

    double* loss_ptr = nullptr;
    cudaGetSymbolAddress((void**)&loss_ptr, g_losssum);

    const int smem_fb = KC * 65 * 4 + KC * 4 + 8 * DD * 4;
    cudaFuncSetAttribute(vq_mma_filter, cudaFuncAttributeMaxDynamicSharedMemorySize, SM_TOT);
    cudaFuncSetAttribute(vq_fallback,   cudaFuncAttributeMaxDynamicSharedMemorySize, smem_fb);

    cudaMemsetAsync(loss_ptr, 0, sizeof(double), 0);

    vq_prep      <<<1, 512>>>(w);
    vq_mma_filter<<<NTILES, 256, SM_TOT>>>(x, w, out_idx, out_q, out_enc, loss_ptr);
    vq_fallback  <<<128, 256, smem_fb>>>(x, w, out_idx, out_q, out_enc, loss_ptr);
    vq_finalize  <<<1, 1>>>(loss_ptr, out_loss);
}